// round 2
// baseline (speedup 1.0000x reference)
#include <cuda_runtime.h>
#include <cstdint>
#include <cstddef>

#define BB 2
#define NN 512
#define HH 128
#define DD 128
#define TT 8
#define ZZ 256
#define NTOT 136

// -------- device scratch (no allocations allowed) --------
__device__ float g_m1[BB*NN*DD];   // z@Wm1 + (bm1+bm2+bme+bmg) + graph@Wmg   [per receiver]
__device__ float g_m2[BB*NN*DD];   // z@Wm2                                    [per sender]
__device__ float g_o1[BB*NN*DD];   // z@Wo1 + bo1 + bo2
__device__ float g_t1[BB*NN*TT];   // z@Wt1 + (bt1+bt2+bte+btg) + graph@Wtg   [per receiver]
__device__ float g_t2[BB*NN*TT];   // z@Wt2                                    [per sender]
__device__ float g_mg[BB*DD];
__device__ float g_tg[BB*TT];
__device__ unsigned g_msgs[BB*NN*DD]; // encoded-float running max

__device__ __forceinline__ float to_tf32(float x){
  unsigned u; asm("cvt.rna.tf32.f32 %0, %1;" : "=r"(u) : "f"(x));
  return __uint_as_float(u);
}
// monotone float->uint encoding (order-preserving for atomicMax)
__device__ __forceinline__ unsigned enc_f(float f){
  unsigned u = __float_as_uint(f);
  return (u & 0x80000000u) ? ~u : (u | 0x80000000u);
}
__device__ __forceinline__ float dec_f(unsigned k){
  unsigned u = (k & 0x80000000u) ? (k & 0x7fffffffu) : ~k;
  return __uint_as_float(u);
}
__device__ __forceinline__ void mma8(float c[4], float a0,float a1,float a2,float a3,
                                     float b0, float b1){
  asm volatile("mma.sync.aligned.m16n8k8.row.col.f32.tf32.tf32.f32 "
      "{%0,%1,%2,%3}, {%4,%5,%6,%7}, {%8,%9}, {%0,%1,%2,%3};\n"
      : "+f"(c[0]), "+f"(c[1]), "+f"(c[2]), "+f"(c[3])
      : "r"(__float_as_uint(a0)), "r"(__float_as_uint(a1)),
        "r"(__float_as_uint(a2)), "r"(__float_as_uint(a3)),
        "r"(__float_as_uint(b0)), "r"(__float_as_uint(b1)));
}

// -------- K0: graph-feature terms + all-bias folding --------
__global__ void k_pre0(const float* __restrict__ graph,
  const float* __restrict__ Wmg, const float* __restrict__ bm1, const float* __restrict__ bm2,
  const float* __restrict__ bme, const float* __restrict__ bmg,
  const float* __restrict__ Wtg, const float* __restrict__ bt1, const float* __restrict__ bt2,
  const float* __restrict__ bte, const float* __restrict__ btg)
{
  int t = threadIdx.x;            // 256 threads
  int b = t >> 7, d = t & 127;
  float s = bm1[d] + bm2[d] + bme[d] + bmg[d];
  for (int h = 0; h < HH; h++) s += graph[b*HH + h] * Wmg[h*DD + d];
  g_mg[t] = s;
  if (t < BB*TT){
    int bb = t >> 3, tt = t & 7;
    float s2 = bt1[tt] + bt2[tt] + bte[tt] + btg[tt];
    for (int h = 0; h < HH; h++) s2 += graph[bb*HH + h] * Wtg[h*TT + tt];
    g_tg[t] = s2;
  }
}

// -------- K1: per-node precompute (m1/m2/o1/t1/t2) --------
__global__ void k_pre1(const float* __restrict__ node, const float* __restrict__ hidden,
  const float* __restrict__ Wm1, const float* __restrict__ Wm2, const float* __restrict__ Wo1,
  const float* __restrict__ Wt1, const float* __restrict__ Wt2,
  const float* __restrict__ bo1, const float* __restrict__ bo2)
{
  __shared__ float z[ZZ];
  int bi = blockIdx.x;            // 0..1023 = b*512 + i
  int b  = bi >> 9;
  int t  = threadIdx.x;           // 128 threads
  z[t]      = node[bi*HH + t];
  z[t + HH] = hidden[bi*HH + t];
  __syncthreads();
  float a1 = 0.f, a2 = 0.f, a3 = 0.f;
  #pragma unroll 8
  for (int h = 0; h < ZZ; h++){
    float zv = z[h];
    a1 += zv * Wm1[h*DD + t];
    a2 += zv * Wm2[h*DD + t];
    a3 += zv * Wo1[h*DD + t];
  }
  g_m1[bi*DD + t] = a1 + g_mg[b*DD + t];
  g_m2[bi*DD + t] = a2;
  g_o1[bi*DD + t] = a3 + bo1[t] + bo2[t];
  if (t < TT){
    float s = 0.f;
    for (int h = 0; h < ZZ; h++) s += z[h] * Wt1[h*TT + t];
    g_t1[bi*TT + t] = s + g_tg[b*TT + t];
  } else if (t < 2*TT){
    int tt = t - TT;
    float s = 0.f;
    for (int h = 0; h < ZZ; h++) s += z[h] * Wt2[h*TT + tt];
    g_t2[bi*TT + tt] = s;
  }
}

__global__ void k_init_msgs(){
  int i = blockIdx.x * 256 + threadIdx.x;
  g_msgs[i] = 0x007fffffu;   // enc(-inf)
}

// -------- K2: main fused edge GEMM + triplet relu + masked max --------
#define RB 64          // receivers per CTA
#define SC 32          // senders per CTA
#define SA_STR 132     // padded A stride (conflict-free frag loads)
#define SW_STR 136     // W stride (naturally conflict-free)
#define SM_STR 132     // padded m1 / rmax stride

#define OFF_W   0
#define OFF_A   (OFF_W  + 128*SW_STR)
#define OFF_M1  (OFF_A  + RB*SA_STR)
#define OFF_T1  (OFF_M1 + RB*SM_STR)
#define OFF_RM  (OFF_T1 + RB*TT)
#define OFF_M2  (OFF_RM + RB*SM_STR)
#define OFF_ADJ (OFF_M2 + NTOT)
#define OFF_ANY (OFF_ADJ + RB)
#define SMEM_WORDS (OFF_ANY + RB)
#define SMEM_BYTES (SMEM_WORDS*4)

__global__ void __launch_bounds__(256,1) k_main(
  const float* __restrict__ edge, const float* __restrict__ adj,
  const float* __restrict__ Wme, const float* __restrict__ Wte,
  float* __restrict__ triOut)
{
  extern __shared__ float smf[];
  float*    sW   = smf + OFF_W;
  float*    sA   = smf + OFF_A;
  float*    sM1  = smf + OFF_M1;
  float*    sT1  = smf + OFF_T1;
  unsigned* sRm  = (unsigned*)(smf + OFF_RM);
  float*    sM2  = smf + OFF_M2;
  float*    sAdj = smf + OFF_ADJ;
  unsigned* sAny = (unsigned*)(smf + OFF_ANY);

  const int tid = threadIdx.x;
  const int b   = blockIdx.z;
  const int r0  = blockIdx.x * RB;
  const int s0  = blockIdx.y * SC;

  // stage weights (tf32) + receiver-side vectors
  for (int i = tid; i < 128*128; i += 256) sW[(i>>7)*SW_STR + (i&127)]       = to_tf32(Wme[i]);
  for (int i = tid; i < 128*8;   i += 256) sW[(i>>3)*SW_STR + 128 + (i&7)]   = to_tf32(Wte[i]);
  {
    const float* p = g_m1 + (size_t)(b*NN + r0)*DD;
    for (int i = tid; i < RB*DD; i += 256) sM1[(i>>7)*SM_STR + (i&127)] = p[i];
    const float* q = g_t1 + (size_t)(b*NN + r0)*TT;
    for (int i = tid; i < RB*TT; i += 256) sT1[i] = q[i];
  }
  for (int i = tid; i < RB*SM_STR; i += 256) sRm[i] = 0x007fffffu;
  if (tid < RB) sAny[tid] = 0u;

  const int w = tid >> 5, lane = tid & 31;
  const int g = lane >> 2, tg4 = lane & 3;
  const int wrow = (w & 3) << 4;
  const bool loW = (w < 4);

  float4 aReg[8];
  float  m2Reg = 0.f, adjReg = 1.f;

  // prologue: load sender s0
  {
    const float* ep = edge + (size_t)((b*NN + s0)*NN + r0)*HH;
    #pragma unroll
    for (int j = 0; j < 8; j++){
      int li = j*256 + tid;
      aReg[j] = *(const float4*)(ep + (li>>5)*HH + (li&31)*4);
    }
    if (tid < DD)        m2Reg = g_m2[(b*NN + s0)*DD + tid];
    else if (tid < NTOT) m2Reg = g_t2[(b*NN + s0)*TT + (tid - DD)];
    if (tid < RB)        adjReg = adj[(size_t)(b*NN + s0)*NN + r0 + tid];
  }

  for (int it = 0; it < SC; ++it){
    const int s = s0 + it;
    // commit staged tile (convert to tf32 on store)
    #pragma unroll
    for (int j = 0; j < 8; j++){
      int li = j*256 + tid;
      float4 v = aReg[j], t;
      t.x = to_tf32(v.x); t.y = to_tf32(v.y); t.z = to_tf32(v.z); t.w = to_tf32(v.w);
      *(float4*)(sA + (li>>5)*SA_STR + (li&31)*4) = t;
    }
    if (tid < NTOT) sM2[tid] = m2Reg;
    if (tid < RB){ sAdj[tid] = adjReg; if (adjReg == 0.f) sAny[tid] = 1u; }
    __syncthreads();

    // prefetch next sender while MMAs run
    if (it + 1 < SC){
      const int sn = s + 1;
      const float* ep = edge + (size_t)((b*NN + sn)*NN + r0)*HH;
      #pragma unroll
      for (int j = 0; j < 8; j++){
        int li = j*256 + tid;
        aReg[j] = *(const float4*)(ep + (li>>5)*HH + (li&31)*4);
      }
      if (tid < DD)        m2Reg = g_m2[(b*NN + sn)*DD + tid];
      else if (tid < NTOT) m2Reg = g_t2[(b*NN + sn)*TT + (tid - DD)];
      if (tid < RB)        adjReg = adj[(size_t)(b*NN + sn)*NN + r0 + tid];
    }

    float C[9][4];
    #pragma unroll
    for (int i = 0; i < 9; i++){ C[i][0]=0.f; C[i][1]=0.f; C[i][2]=0.f; C[i][3]=0.f; }

    #pragma unroll
    for (int ks = 0; ks < 16; ks++){
      const int k0 = ks << 3;
      const float* ar0 = sA + (wrow + g)*SA_STR + k0 + tg4;
      const float* ar1 = ar0 + 8*SA_STR;
      float a0 = ar0[0], a1 = ar1[0], a2 = ar0[4], a3 = ar1[4];
      const float* bw0 = sW + (k0 + tg4)*SW_STR + g;
      const float* bw1 = bw0 + 4*SW_STR;
      if (loW){
        #pragma unroll
        for (int ni = 0; ni < 9; ni++)
          mma8(C[ni], a0,a1,a2,a3, bw0[8*ni], bw1[8*ni]);
      } else {
        #pragma unroll
        for (int ni = 0; ni < 8; ni++)
          mma8(C[ni], a0,a1,a2,a3, bw0[72 + 8*ni], bw1[72 + 8*ni]);
      }
    }

    // epilogue
    const int rr0 = wrow + g, rr1 = rr0 + 8;
    const float adj0 = sAdj[rr0], adj1 = sAdj[rr1];
    if (loW){
      #pragma unroll
      for (int ni = 0; ni < 9; ni++){
        const int n = 8*ni + 2*tg4;
        float v00 = C[ni][0] + sM1[rr0*SM_STR + n]     + sM2[n];
        float v01 = C[ni][1] + sM1[rr0*SM_STR + n + 1] + sM2[n+1];
        float v10 = C[ni][2] + sM1[rr1*SM_STR + n]     + sM2[n];
        float v11 = C[ni][3] + sM1[rr1*SM_STR + n + 1] + sM2[n+1];
        if (adj0 != 0.f){
          atomicMax(&sRm[rr0*SM_STR + n],     enc_f(v00));
          atomicMax(&sRm[rr0*SM_STR + n + 1], enc_f(v01));
        }
        if (adj1 != 0.f){
          atomicMax(&sRm[rr1*SM_STR + n],     enc_f(v10));
          atomicMax(&sRm[rr1*SM_STR + n + 1], enc_f(v11));
        }
      }
    } else {
      #pragma unroll
      for (int ni = 0; ni < 7; ni++){
        const int n = 72 + 8*ni + 2*tg4;
        float v00 = C[ni][0] + sM1[rr0*SM_STR + n]     + sM2[n];
        float v01 = C[ni][1] + sM1[rr0*SM_STR + n + 1] + sM2[n+1];
        float v10 = C[ni][2] + sM1[rr1*SM_STR + n]     + sM2[n];
        float v11 = C[ni][3] + sM1[rr1*SM_STR + n + 1] + sM2[n+1];
        if (adj0 != 0.f){
          atomicMax(&sRm[rr0*SM_STR + n],     enc_f(v00));
          atomicMax(&sRm[rr0*SM_STR + n + 1], enc_f(v01));
        }
        if (adj1 != 0.f){
          atomicMax(&sRm[rr1*SM_STR + n],     enc_f(v10));
          atomicMax(&sRm[rr1*SM_STR + n + 1], enc_f(v11));
        }
      }
      { // ni == 7: triplet columns 128..135 -> relu -> store
        const int tc = 2*tg4;
        float v00 = C[7][0] + sT1[rr0*TT + tc]     + sM2[128 + tc];
        float v01 = C[7][1] + sT1[rr0*TT + tc + 1] + sM2[128 + tc + 1];
        float v10 = C[7][2] + sT1[rr1*TT + tc]     + sM2[128 + tc];
        float v11 = C[7][3] + sT1[rr1*TT + tc + 1] + sM2[128 + tc + 1];
        size_t base = (size_t)((b*NN + s)*NN) + r0;
        float* o0 = triOut + (base + rr0)*TT + tc;
        float* o1 = triOut + (base + rr1)*TT + tc;
        o0[0] = fmaxf(v00, 0.f); o0[1] = fmaxf(v01, 0.f);
        o1[0] = fmaxf(v10, 0.f); o1[1] = fmaxf(v11, 0.f);
      }
    }
    __syncthreads();
  }

  // flush per-CTA running max to global (encoded uint atomicMax)
  for (int i = tid; i < RB*DD; i += 256){
    const int rl = i >> 7, c = i & 127;
    unsigned e = sRm[rl*SM_STR + c];
    if (sAny[rl] && e < 0x80000000u) e = 0x80000000u;   // enc(0.0f) from masked senders
    atomicMax(&g_msgs[(size_t)(b*NN + r0 + rl)*DD + c], e);
  }
}

// -------- K3: ret = o1full + msgs @ Wo2 --------
__global__ void k_out(const float* __restrict__ Wo2, float* __restrict__ ret){
  __shared__ float sm[DD];
  int bi = blockIdx.x;
  int d  = threadIdx.x;
  sm[d] = dec_f(g_msgs[(size_t)bi*DD + d]);
  __syncthreads();
  float acc = g_o1[(size_t)bi*DD + d];
  #pragma unroll 8
  for (int c = 0; c < DD; c++) acc += sm[c] * Wo2[c*DD + d];
  ret[(size_t)bi*DD + d] = acc;
}

// -------- launcher --------
extern "C" void kernel_launch(void* const* d_in, const int* in_sizes, int n_in,
                              void* d_out, int out_size){
  const float* node   = (const float*)d_in[0];
  const float* edge   = (const float*)d_in[1];
  const float* graph  = (const float*)d_in[2];
  const float* adjm   = (const float*)d_in[3];
  const float* hidden = (const float*)d_in[4];
  const float* Wm1 = (const float*)d_in[5];  const float* bm1 = (const float*)d_in[6];
  const float* Wm2 = (const float*)d_in[7];  const float* bm2 = (const float*)d_in[8];
  const float* Wme = (const float*)d_in[9];  const float* bme = (const float*)d_in[10];
  const float* Wmg = (const float*)d_in[11]; const float* bmg = (const float*)d_in[12];
  const float* Wo1 = (const float*)d_in[13]; const float* bo1 = (const float*)d_in[14];
  const float* Wo2 = (const float*)d_in[15]; const float* bo2 = (const float*)d_in[16];
  const float* Wt1 = (const float*)d_in[17]; const float* bt1 = (const float*)d_in[18];
  const float* Wt2 = (const float*)d_in[19]; const float* bt2 = (const float*)d_in[20];
  const float* Wte = (const float*)d_in[21]; const float* bte = (const float*)d_in[22];
  const float* Wtg = (const float*)d_in[23]; const float* btg = (const float*)d_in[24];

  float* ret = (float*)d_out;                 // [2,512,128]
  float* tri = ret + (size_t)BB*NN*DD;        // [2,512,512,8]

  cudaFuncSetAttribute(k_main, cudaFuncAttributeMaxDynamicSharedMemorySize, SMEM_BYTES);

  k_pre0<<<1, 256>>>(graph, Wmg, bm1, bm2, bme, bmg, Wtg, bt1, bt2, bte, btg);
  k_pre1<<<BB*NN, 128>>>(node, hidden, Wm1, Wm2, Wo1, Wt1, Wt2, bo1, bo2);
  k_init_msgs<<<(BB*NN*DD)/256, 256>>>();
  k_main<<<dim3(NN/RB, NN/SC, BB), 256, SMEM_BYTES>>>(edge, adjm, Wme, Wte, tri);
  k_out<<<BB*NN, DD>>>(Wo2, ret);
}

// round 4
// speedup vs baseline: 1.0082x; 1.0082x over previous
#include <cuda_runtime.h>
#include <cstdint>
#include <cstddef>

#define BB 2
#define NN 512
#define HH 128
#define DD 128
#define TT 8
#define ZZ 256
#define NTOT 136

// -------- device scratch (no allocations allowed) --------
__device__ float g_m1[BB*NN*DD];   // z@Wm1 + (bm1+bm2+bme+bmg) + graph@Wmg   [per receiver]
__device__ float g_m2[BB*NN*DD];   // z@Wm2                                    [per sender]
__device__ float g_o1[BB*NN*DD];   // z@Wo1 + bo1 + bo2
__device__ float g_t1[BB*NN*TT];   // z@Wt1 + (bt1+bt2+bte+btg) + graph@Wtg   [per receiver]
__device__ float g_t2[BB*NN*TT];   // z@Wt2                                    [per sender]
__device__ float g_mg[BB*DD];
__device__ float g_tg[BB*TT];
__device__ unsigned g_msgs[BB*NN*DD]; // encoded-float running max

__device__ __forceinline__ float to_tf32(float x){
  unsigned u; asm("cvt.rna.tf32.f32 %0, %1;" : "=r"(u) : "f"(x));
  return __uint_as_float(u);
}
// monotone float->uint encoding (order-preserving for atomicMax)
__device__ __forceinline__ unsigned enc_f(float f){
  unsigned u = __float_as_uint(f);
  return (u & 0x80000000u) ? ~u : (u | 0x80000000u);
}
__device__ __forceinline__ float dec_f(unsigned k){
  unsigned u = (k & 0x80000000u) ? (k & 0x7fffffffu) : ~k;
  return __uint_as_float(u);
}
__device__ __forceinline__ void mma8(float c[4], float a0,float a1,float a2,float a3,
                                     float b0, float b1){
  asm volatile("mma.sync.aligned.m16n8k8.row.col.f32.tf32.tf32.f32 "
      "{%0,%1,%2,%3}, {%4,%5,%6,%7}, {%8,%9}, {%0,%1,%2,%3};\n"
      : "+f"(c[0]), "+f"(c[1]), "+f"(c[2]), "+f"(c[3])
      : "r"(__float_as_uint(a0)), "r"(__float_as_uint(a1)),
        "r"(__float_as_uint(a2)), "r"(__float_as_uint(a3)),
        "r"(__float_as_uint(b0)), "r"(__float_as_uint(b1)));
}

// -------- K0: graph-feature terms + all-bias folding --------
__global__ void k_pre0(const float* __restrict__ graph,
  const float* __restrict__ Wmg, const float* __restrict__ bm1, const float* __restrict__ bm2,
  const float* __restrict__ bme, const float* __restrict__ bmg,
  const float* __restrict__ Wtg, const float* __restrict__ bt1, const float* __restrict__ bt2,
  const float* __restrict__ bte, const float* __restrict__ btg)
{
  int t = threadIdx.x;            // 256 threads
  int b = t >> 7, d = t & 127;
  float s = bm1[d] + bm2[d] + bme[d] + bmg[d];
  for (int h = 0; h < HH; h++) s += graph[b*HH + h] * Wmg[h*DD + d];
  g_mg[t] = s;
  if (t < BB*TT){
    int bb = t >> 3, tt = t & 7;
    float s2 = bt1[tt] + bt2[tt] + bte[tt] + btg[tt];
    for (int h = 0; h < HH; h++) s2 += graph[bb*HH + h] * Wtg[h*TT + tt];
    g_tg[t] = s2;
  }
}

// -------- K1: per-node precompute (m1/m2/o1/t1/t2) --------
__global__ void k_pre1(const float* __restrict__ node, const float* __restrict__ hidden,
  const float* __restrict__ Wm1, const float* __restrict__ Wm2, const float* __restrict__ Wo1,
  const float* __restrict__ Wt1, const float* __restrict__ Wt2,
  const float* __restrict__ bo1, const float* __restrict__ bo2)
{
  __shared__ float z[ZZ];
  int bi = blockIdx.x;            // 0..1023 = b*512 + i
  int b  = bi >> 9;
  int t  = threadIdx.x;           // 128 threads
  z[t]      = node[bi*HH + t];
  z[t + HH] = hidden[bi*HH + t];
  __syncthreads();
  float a1 = 0.f, a2 = 0.f, a3 = 0.f;
  #pragma unroll 8
  for (int h = 0; h < ZZ; h++){
    float zv = z[h];
    a1 += zv * Wm1[h*DD + t];
    a2 += zv * Wm2[h*DD + t];
    a3 += zv * Wo1[h*DD + t];
  }
  g_m1[bi*DD + t] = a1 + g_mg[b*DD + t];
  g_m2[bi*DD + t] = a2;
  g_o1[bi*DD + t] = a3 + bo1[t] + bo2[t];
  if (t < TT){
    float s = 0.f;
    for (int h = 0; h < ZZ; h++) s += z[h] * Wt1[h*TT + t];
    g_t1[bi*TT + t] = s + g_tg[b*TT + t];
  } else if (t < 2*TT){
    int tt = t - TT;
    float s = 0.f;
    for (int h = 0; h < ZZ; h++) s += z[h] * Wt2[h*TT + tt];
    g_t2[bi*TT + tt] = s;
  }
}

__global__ void k_init_msgs(){
  int i = blockIdx.x * 256 + threadIdx.x;
  g_msgs[i] = 0x007fffffu;   // enc(-inf)
}

// -------- K2: main fused edge GEMM + triplet relu + masked max --------
#define RB 64          // receivers per CTA
#define SC 32          // senders per CTA
#define SA_STR 132     // padded A stride (conflict-free frag loads)
#define SW_STR 136     // W stride (naturally conflict-free)
#define SM_STR 132     // padded m1 / rmax stride

#define OFF_W   0
#define OFF_A   (OFF_W  + 128*SW_STR)
#define OFF_M1  (OFF_A  + RB*SA_STR)
#define OFF_T1  (OFF_M1 + RB*SM_STR)
#define OFF_RM  (OFF_T1 + RB*TT)
#define OFF_M2  (OFF_RM + RB*SM_STR)
#define OFF_ADJ (OFF_M2 + NTOT)
#define OFF_ANY (OFF_ADJ + RB)
#define SMEM_WORDS (OFF_ANY + RB)
#define SMEM_BYTES (SMEM_WORDS*4)

__global__ void __launch_bounds__(256,1) k_main(
  const float* __restrict__ edge, const float* __restrict__ adj,
  const float* __restrict__ Wme, const float* __restrict__ Wte,
  float* __restrict__ triOut)
{
  extern __shared__ float smf[];
  float*    sW   = smf + OFF_W;
  float*    sA   = smf + OFF_A;
  float*    sM1  = smf + OFF_M1;
  float*    sT1  = smf + OFF_T1;
  unsigned* sRm  = (unsigned*)(smf + OFF_RM);
  float*    sM2  = smf + OFF_M2;
  float*    sAdj = smf + OFF_ADJ;
  unsigned* sAny = (unsigned*)(smf + OFF_ANY);

  const int tid = threadIdx.x;
  const int b   = blockIdx.z;
  const int r0  = blockIdx.x * RB;
  const int s0  = blockIdx.y * SC;

  // stage weights (tf32) + receiver-side vectors
  for (int i = tid; i < 128*128; i += 256) sW[(i>>7)*SW_STR + (i&127)]       = to_tf32(Wme[i]);
  for (int i = tid; i < 128*8;   i += 256) sW[(i>>3)*SW_STR + 128 + (i&7)]   = to_tf32(Wte[i]);
  {
    const float* p = g_m1 + (size_t)(b*NN + r0)*DD;
    for (int i = tid; i < RB*DD; i += 256) sM1[(i>>7)*SM_STR + (i&127)] = p[i];
    const float* q = g_t1 + (size_t)(b*NN + r0)*TT;
    for (int i = tid; i < RB*TT; i += 256) sT1[i] = q[i];
  }
  for (int i = tid; i < RB*SM_STR; i += 256) sRm[i] = 0x007fffffu;
  if (tid < RB) sAny[tid] = 0u;

  const int w = tid >> 5, lane = tid & 31;
  const int g = lane >> 2, tg4 = lane & 3;
  const int wrow = (w & 3) << 4;
  const bool loW = (w < 4);

  float4 aReg[8];
  float  m2Reg = 0.f, adjReg = 1.f;

  // prologue: load sender s0
  {
    const float* ep = edge + (size_t)((b*NN + s0)*NN + r0)*HH;
    #pragma unroll
    for (int j = 0; j < 8; j++){
      int li = j*256 + tid;
      aReg[j] = *(const float4*)(ep + (li>>5)*HH + (li&31)*4);
    }
    if (tid < DD)        m2Reg = g_m2[(b*NN + s0)*DD + tid];
    else if (tid < NTOT) m2Reg = g_t2[(b*NN + s0)*TT + (tid - DD)];
    if (tid < RB)        adjReg = adj[(size_t)(b*NN + s0)*NN + r0 + tid];
  }

  for (int it = 0; it < SC; ++it){
    const int s = s0 + it;
    // commit staged tile (convert to tf32 on store)
    #pragma unroll
    for (int j = 0; j < 8; j++){
      int li = j*256 + tid;
      float4 v = aReg[j], t;
      t.x = to_tf32(v.x); t.y = to_tf32(v.y); t.z = to_tf32(v.z); t.w = to_tf32(v.w);
      *(float4*)(sA + (li>>5)*SA_STR + (li&31)*4) = t;
    }
    if (tid < NTOT) sM2[tid] = m2Reg;
    if (tid < RB){ sAdj[tid] = adjReg; if (adjReg == 0.f) sAny[tid] = 1u; }
    __syncthreads();

    // prefetch next sender while MMAs run
    if (it + 1 < SC){
      const int sn = s + 1;
      const float* ep = edge + (size_t)((b*NN + sn)*NN + r0)*HH;
      #pragma unroll
      for (int j = 0; j < 8; j++){
        int li = j*256 + tid;
        aReg[j] = *(const float4*)(ep + (li>>5)*HH + (li&31)*4);
      }
      if (tid < DD)        m2Reg = g_m2[(b*NN + sn)*DD + tid];
      else if (tid < NTOT) m2Reg = g_t2[(b*NN + sn)*TT + (tid - DD)];
      if (tid < RB)        adjReg = adj[(size_t)(b*NN + sn)*NN + r0 + tid];
    }

    float C[9][4];
    #pragma unroll
    for (int i = 0; i < 9; i++){ C[i][0]=0.f; C[i][1]=0.f; C[i][2]=0.f; C[i][3]=0.f; }

    #pragma unroll
    for (int ks = 0; ks < 16; ks++){
      const int k0 = ks << 3;
      const float* ar0 = sA + (wrow + g)*SA_STR + k0 + tg4;
      const float* ar1 = ar0 + 8*SA_STR;
      float a0 = ar0[0], a1 = ar1[0], a2 = ar0[4], a3 = ar1[4];
      const float* bw0 = sW + (k0 + tg4)*SW_STR + g;
      const float* bw1 = bw0 + 4*SW_STR;
      if (loW){
        #pragma unroll
        for (int ni = 0; ni < 9; ni++)
          mma8(C[ni], a0,a1,a2,a3, bw0[8*ni], bw1[8*ni]);
      } else {
        #pragma unroll
        for (int ni = 0; ni < 8; ni++)
          mma8(C[ni], a0,a1,a2,a3, bw0[72 + 8*ni], bw1[72 + 8*ni]);
      }
    }

    // epilogue
    const int rr0 = wrow + g, rr1 = rr0 + 8;
    const float adj0 = sAdj[rr0], adj1 = sAdj[rr1];
    if (loW){
      #pragma unroll
      for (int ni = 0; ni < 9; ni++){
        const int n = 8*ni + 2*tg4;
        float v00 = C[ni][0] + sM1[rr0*SM_STR + n]     + sM2[n];
        float v01 = C[ni][1] + sM1[rr0*SM_STR + n + 1] + sM2[n+1];
        float v10 = C[ni][2] + sM1[rr1*SM_STR + n]     + sM2[n];
        float v11 = C[ni][3] + sM1[rr1*SM_STR + n + 1] + sM2[n+1];
        if (adj0 != 0.f){
          atomicMax(&sRm[rr0*SM_STR + n],     enc_f(v00));
          atomicMax(&sRm[rr0*SM_STR + n + 1], enc_f(v01));
        }
        if (adj1 != 0.f){
          atomicMax(&sRm[rr1*SM_STR + n],     enc_f(v10));
          atomicMax(&sRm[rr1*SM_STR + n + 1], enc_f(v11));
        }
      }
    } else {
      #pragma unroll
      for (int ni = 0; ni < 7; ni++){
        const int n = 72 + 8*ni + 2*tg4;
        float v00 = C[ni][0] + sM1[rr0*SM_STR + n]     + sM2[n];
        float v01 = C[ni][1] + sM1[rr0*SM_STR + n + 1] + sM2[n+1];
        float v10 = C[ni][2] + sM1[rr1*SM_STR + n]     + sM2[n];
        float v11 = C[ni][3] + sM1[rr1*SM_STR + n + 1] + sM2[n+1];
        if (adj0 != 0.f){
          atomicMax(&sRm[rr0*SM_STR + n],     enc_f(v00));
          atomicMax(&sRm[rr0*SM_STR + n + 1], enc_f(v01));
        }
        if (adj1 != 0.f){
          atomicMax(&sRm[rr1*SM_STR + n],     enc_f(v10));
          atomicMax(&sRm[rr1*SM_STR + n + 1], enc_f(v11));
        }
      }
      { // ni == 7: triplet columns 128..135 -> relu -> store
        const int tc = 2*tg4;
        float v00 = C[7][0] + sT1[rr0*TT + tc]     + sM2[128 + tc];
        float v01 = C[7][1] + sT1[rr0*TT + tc + 1] + sM2[128 + tc + 1];
        float v10 = C[7][2] + sT1[rr1*TT + tc]     + sM2[128 + tc];
        float v11 = C[7][3] + sT1[rr1*TT + tc + 1] + sM2[128 + tc + 1];
        size_t base = (size_t)((b*NN + s)*NN) + r0;
        float* o0 = triOut + (base + rr0)*TT + tc;
        float* o1 = triOut + (base + rr1)*TT + tc;
        o0[0] = fmaxf(v00, 0.f); o0[1] = fmaxf(v01, 0.f);
        o1[0] = fmaxf(v10, 0.f); o1[1] = fmaxf(v11, 0.f);
      }
    }
    __syncthreads();
  }

  // flush per-CTA running max to global (encoded uint atomicMax)
  for (int i = tid; i < RB*DD; i += 256){
    const int rl = i >> 7, c = i & 127;
    unsigned e = sRm[rl*SM_STR + c];
    if (sAny[rl] && e < 0x80000000u) e = 0x80000000u;   // enc(0.0f) from masked senders
    atomicMax(&g_msgs[(size_t)(b*NN + r0 + rl)*DD + c], e);
  }
}

// -------- K3: ret = o1full + msgs @ Wo2 --------
__global__ void k_out(const float* __restrict__ Wo2, float* __restrict__ ret){
  __shared__ float sm[DD];
  int bi = blockIdx.x;
  int d  = threadIdx.x;
  sm[d] = dec_f(g_msgs[(size_t)bi*DD + d]);
  __syncthreads();
  float acc = g_o1[(size_t)bi*DD + d];
  #pragma unroll 8
  for (int c = 0; c < DD; c++) acc += sm[c] * Wo2[c*DD + d];
  ret[(size_t)bi*DD + d] = acc;
}

// -------- launcher --------
extern "C" void kernel_launch(void* const* d_in, const int* in_sizes, int n_in,
                              void* d_out, int out_size){
  const float* node   = (const float*)d_in[0];
  const float* edge   = (const float*)d_in[1];
  const float* graph  = (const float*)d_in[2];
  const float* adjm   = (const float*)d_in[3];
  const float* hidden = (const float*)d_in[4];
  const float* Wm1 = (const float*)d_in[5];  const float* bm1 = (const float*)d_in[6];
  const float* Wm2 = (const float*)d_in[7];  const float* bm2 = (const float*)d_in[8];
  const float* Wme = (const float*)d_in[9];  const float* bme = (const float*)d_in[10];
  const float* Wmg = (const float*)d_in[11]; const float* bmg = (const float*)d_in[12];
  const float* Wo1 = (const float*)d_in[13]; const float* bo1 = (const float*)d_in[14];
  const float* Wo2 = (const float*)d_in[15]; const float* bo2 = (const float*)d_in[16];
  const float* Wt1 = (const float*)d_in[17]; const float* bt1 = (const float*)d_in[18];
  const float* Wt2 = (const float*)d_in[19]; const float* bt2 = (const float*)d_in[20];
  const float* Wte = (const float*)d_in[21]; const float* bte = (const float*)d_in[22];
  const float* Wtg = (const float*)d_in[23]; const float* btg = (const float*)d_in[24];

  float* ret = (float*)d_out;                 // [2,512,128]
  float* tri = ret + (size_t)BB*NN*DD;        // [2,512,512,8]

  cudaFuncSetAttribute(k_main, cudaFuncAttributeMaxDynamicSharedMemorySize, SMEM_BYTES);

  k_pre0<<<1, 256>>>(graph, Wmg, bm1, bm2, bme, bmg, Wtg, bt1, bt2, bte, btg);
  k_pre1<<<BB*NN, 128>>>(node, hidden, Wm1, Wm2, Wo1, Wt1, Wt2, bo1, bo2);
  k_init_msgs<<<(BB*NN*DD)/256, 256>>>();
  k_main<<<dim3(NN/RB, NN/SC, BB), 256, SMEM_BYTES>>>(edge, adjm, Wme, Wte, tri);
  k_out<<<BB*NN, DD>>>(Wo2, ret);
}

// round 7
// speedup vs baseline: 1.2909x; 1.2805x over previous
#include <cuda_runtime.h>
#include <cstdint>
#include <cstddef>

#define BB 2
#define NN 512
#define HH 128
#define DD 128
#define TT 8
#define ZZ 256
#define NTOT 136

// -------- device scratch --------
__device__ float g_m1[BB*NN*DD];   // z@Wm1 + (all msg biases) + graph@Wmg  [receiver]
__device__ float g_m2[BB*NN*DD];   // z@Wm2                                 [sender]
__device__ float g_o1[BB*NN*DD];   // z@Wo1 + bo1 + bo2
__device__ float g_t1[BB*NN*TT];   // z@Wt1 + (all tri biases) + graph@Wtg  [receiver]
__device__ float g_t2[BB*NN*TT];   // z@Wt2                                 [sender]
__device__ float g_mg[BB*DD];
__device__ float g_tg[BB*TT];
__device__ unsigned g_msgs[BB*NN*DD]; // encoded-float running max

__device__ __forceinline__ float to_tf32(float x){
  unsigned u; asm("cvt.rna.tf32.f32 %0, %1;" : "=r"(u) : "f"(x));
  return __uint_as_float(u);
}
__device__ __forceinline__ unsigned enc_f(float f){
  unsigned u = __float_as_uint(f);
  return (u & 0x80000000u) ? ~u : (u | 0x80000000u);
}
__device__ __forceinline__ float dec_f(unsigned k){
  unsigned u = (k & 0x80000000u) ? (k & 0x7fffffffu) : ~k;
  return __uint_as_float(u);
}
__device__ __forceinline__ void mma8(float c[4], float a0,float a1,float a2,float a3,
                                     float b0, float b1){
  asm volatile("mma.sync.aligned.m16n8k8.row.col.f32.tf32.tf32.f32 "
      "{%0,%1,%2,%3}, {%4,%5,%6,%7}, {%8,%9}, {%0,%1,%2,%3};\n"
      : "+f"(c[0]), "+f"(c[1]), "+f"(c[2]), "+f"(c[3])
      : "r"(__float_as_uint(a0)), "r"(__float_as_uint(a1)),
        "r"(__float_as_uint(a2)), "r"(__float_as_uint(a3)),
        "r"(__float_as_uint(b0)), "r"(__float_as_uint(b1)));
}
__device__ __forceinline__ void cp16(void* smem, const void* gmem){
  unsigned s = (unsigned)__cvta_generic_to_shared(smem);
  asm volatile("cp.async.cg.shared.global [%0], [%1], 16;\n" :: "r"(s), "l"(gmem));
}
#define CP_COMMIT() asm volatile("cp.async.commit_group;\n" ::: "memory")
#define CP_WAIT1()  asm volatile("cp.async.wait_group 1;\n" ::: "memory")
#define CP_WAIT0()  asm volatile("cp.async.wait_group 0;\n" ::: "memory")

// -------- K0: graph terms + bias folding --------
__global__ void k_pre0(const float* __restrict__ graph,
  const float* __restrict__ Wmg, const float* __restrict__ bm1, const float* __restrict__ bm2,
  const float* __restrict__ bme, const float* __restrict__ bmg,
  const float* __restrict__ Wtg, const float* __restrict__ bt1, const float* __restrict__ bt2,
  const float* __restrict__ bte, const float* __restrict__ btg)
{
  int t = threadIdx.x;            // 256 threads
  int b = t >> 7, d = t & 127;
  float s = bm1[d] + bm2[d] + bme[d] + bmg[d];
  for (int h = 0; h < HH; h++) s += graph[b*HH + h] * Wmg[h*DD + d];
  g_mg[t] = s;
  if (t < BB*TT){
    int bb = t >> 3, tt = t & 7;
    float s2 = bt1[tt] + bt2[tt] + bte[tt] + btg[tt];
    for (int h = 0; h < HH; h++) s2 += graph[bb*HH + h] * Wtg[h*TT + tt];
    g_tg[t] = s2;
  }
}

// -------- K1: per-node precompute, tiled (8 nodes/block, h split in halves) ----
__global__ void __launch_bounds__(256) k_pre1(
  const float* __restrict__ node, const float* __restrict__ hidden,
  const float* __restrict__ Wm1, const float* __restrict__ Wm2, const float* __restrict__ Wo1,
  const float* __restrict__ Wt1, const float* __restrict__ Wt2,
  const float* __restrict__ bo1, const float* __restrict__ bo2)
{
  __shared__ float z[8][256];          // 8 KB
  __shared__ float red[2][3][8][128];  // 24 KB
  const int nb0 = blockIdx.x * 8;
  const int tid = threadIdx.x;
  for (int idx = tid; idx < 8*256; idx += 256){
    int i = idx >> 8, h = idx & 255;
    int bi = nb0 + i;
    z[i][h] = (h < HH) ? node[bi*HH + h] : hidden[bi*HH + (h - HH)];
  }
  __syncthreads();
  const int d = tid & 127, hv = tid >> 7;
  float a1[8], a2[8], a3[8];
  #pragma unroll
  for (int i = 0; i < 8; i++){ a1[i]=0.f; a2[i]=0.f; a3[i]=0.f; }
  const int h0 = hv * 128;
  for (int hh = 0; hh < 128; hh++){
    int h = h0 + hh;
    float w1 = Wm1[h*DD + d], w2 = Wm2[h*DD + d], w3 = Wo1[h*DD + d];
    #pragma unroll
    for (int i = 0; i < 8; i++){
      float zv = z[i][h];
      a1[i] += zv * w1; a2[i] += zv * w2; a3[i] += zv * w3;
    }
  }
  #pragma unroll
  for (int i = 0; i < 8; i++){
    red[hv][0][i][d] = a1[i]; red[hv][1][i][d] = a2[i]; red[hv][2][i][d] = a3[i];
  }
  __syncthreads();
  for (int idx = tid; idx < 1024; idx += 256){
    int i = idx >> 7, dd = idx & 127;
    int bi = nb0 + i, b = bi >> 9;
    float v1 = red[0][0][i][dd] + red[1][0][i][dd];
    float v2 = red[0][1][i][dd] + red[1][1][i][dd];
    float v3 = red[0][2][i][dd] + red[1][2][i][dd];
    g_m1[(size_t)bi*DD + dd] = v1 + g_mg[b*DD + dd];
    g_m2[(size_t)bi*DD + dd] = v2;
    g_o1[(size_t)bi*DD + dd] = v3 + bo1[dd] + bo2[dd];
  }
  if (tid < 128){
    int i = tid >> 4, t = (tid >> 1) & 7, m = tid & 1;
    const float* W = m ? Wt2 : Wt1;
    float s = 0.f;
    for (int h = 0; h < ZZ; h++) s += z[i][h] * W[h*TT + t];
    int bi = nb0 + i, b = bi >> 9;
    if (m == 0) g_t1[(size_t)bi*TT + t] = s + g_tg[b*TT + t];
    else        g_t2[(size_t)bi*TT + t] = s;
  }
}

__global__ void k_init_msgs(){
  int i = blockIdx.x * 256 + threadIdx.x;
  g_msgs[i] = 0x007fffffu;   // enc(-inf)
}

// -------- K2: main fused edge GEMM + triplet relu + masked max --------
#define RB 64
#define SC 32
#define WSTR 136                  // W2 row stride in float2 (NO overflow; uniform degree-2 banks)
// smem layout (float offsets)
#define OFF_W2   0                      // 64 rows x 136 float2 = 17408 floats
#define OFF_A    (64*WSTR*2)            // 17408: 2 bufs x 2 senders x 64x132
#define OFF_M2   (OFF_A + 2*2*64*132)   // 51200: 2 bufs x 2 x 136
#define OFF_ADJ  (OFF_M2 + 2*2*136)     // 51744: 2 bufs x 2 x 64
#define OFF_T1   (OFF_ADJ + 2*2*64)     // 52000: 64 x 8
#define SMEM_WORDS (OFF_T1 + 64*8)      // 52512
#define SMEM_BYTES (SMEM_WORDS*4)       // 210048

__device__ __forceinline__ void prefetch_step(float* smf, const float* edge,
  const float* adj, int b, int r0, int sbase, int buf, int tid)
{
  float* Ab = smf + OFF_A + buf*(2*64*132);
  #pragma unroll
  for (int i = 0; i < 16; i++){
    int idx = i*256 + tid;
    int jj = i >> 3;                 // sender within pair
    int s  = sbase + jj;
    int r  = (idx >> 5) & 63;
    int c  = idx & 31;
    const float* gp = edge + ((size_t)(b*NN + s)*NN + r0 + r)*HH + c*4;
    cp16(Ab + jj*(64*132) + r*132 + c*4, gp);
  }
  if (tid < 64){
    int jj = tid >> 5, c = tid & 31;
    int s = sbase + jj;
    cp16(smf + OFF_M2 + buf*272 + jj*136 + c*4, g_m2 + (size_t)(b*NN + s)*DD + c*4);
  } else if (tid < 68){
    int q = tid - 64; int jj = q >> 1, c = q & 1;
    int s = sbase + jj;
    cp16(smf + OFF_M2 + buf*272 + jj*136 + 128 + c*4, g_t2 + (size_t)(b*NN + s)*TT + c*4);
  } else if (tid < 100){
    int q = tid - 68; int jj = q >> 4, c = q & 15;
    int s = sbase + jj;
    cp16(smf + OFF_ADJ + buf*128 + jj*64 + c*4, adj + (size_t)(b*NN + s)*NN + r0 + c*4);
  }
}

template<int NI, int NBASE, bool TRI>
__device__ __forceinline__ void step_compute(
  const float* __restrict__ smf, int buf, int wrow, int g, int tg4,
  float rm[9][4], bool& anyM0, bool& anyM1,
  int b, int r0, int sstep, float* __restrict__ triOut)
{
  const float* A0 = smf + OFF_A + buf*(2*64*132) + (wrow + g)*132 + tg4;
  const float* A1 = A0 + 64*132;
  const float2* Wp = (const float2*)smf + (size_t)tg4*WSTR + NBASE + g;

  float C0[NI][4], C1[NI][4];
  #pragma unroll
  for (int i = 0; i < NI; i++){
    C0[i][0]=0.f; C0[i][1]=0.f; C0[i][2]=0.f; C0[i][3]=0.f;
    C1[i][0]=0.f; C1[i][1]=0.f; C1[i][2]=0.f; C1[i][3]=0.f;
  }

  #pragma unroll 4
  for (int ks = 0; ks < 16; ks++){
    const float* a0 = A0 + ks*8;
    float x0 = to_tf32(a0[0]), x1 = to_tf32(a0[8*132]);
    float x2 = to_tf32(a0[4]), x3 = to_tf32(a0[8*132 + 4]);
    const float* a1 = A1 + ks*8;
    float y0 = to_tf32(a1[0]), y1 = to_tf32(a1[8*132]);
    float y2 = to_tf32(a1[4]), y3 = to_tf32(a1[8*132 + 4]);
    const float2* wp = Wp + ks*4*WSTR;
    #pragma unroll
    for (int ni = 0; ni < NI; ni++){
      float2 bb = wp[ni*8];
      mma8(C0[ni], x0,x1,x2,x3, bb.x, bb.y);
      mma8(C1[ni], y0,y1,y2,y3, bb.x, bb.y);
    }
  }

  #pragma unroll
  for (int j = 0; j < 2; j++){
    const float* M2 = smf + OFF_M2 + buf*272 + j*136;
    const float* AD = smf + OFF_ADJ + buf*128 + j*64;
    float adjA = AD[wrow + g];
    float adjB = AD[wrow + 8 + g];
    if (adjA == 0.f) anyM0 = true;
    if (adjB == 0.f) anyM1 = true;
    const float (*C)[4] = j ? C1 : C0;
    const int NM = TRI ? (NI - 1) : NI;
    #pragma unroll
    for (int ni = 0; ni < NM; ni++){
      int n = NBASE + 8*ni + 2*tg4;
      float2 m2 = *(const float2*)(M2 + n);
      if (adjA != 0.f){
        rm[ni][0] = fmaxf(rm[ni][0], C[ni][0] + m2.x);
        rm[ni][1] = fmaxf(rm[ni][1], C[ni][1] + m2.y);
      }
      if (adjB != 0.f){
        rm[ni][2] = fmaxf(rm[ni][2], C[ni][2] + m2.x);
        rm[ni][3] = fmaxf(rm[ni][3], C[ni][3] + m2.y);
      }
    }
    if (TRI){
      int tc = 2*tg4;
      float2 m2t = *(const float2*)(M2 + 128 + tc);
      const float* T1 = smf + OFF_T1;
      float2 tA = *(const float2*)(T1 + (wrow + g)*TT + tc);
      float2 tB = *(const float2*)(T1 + (wrow + 8 + g)*TT + tc);
      int s = sstep + j;
      size_t base = (size_t)(b*NN + s)*NN + r0;
      float2 oA, oB;
      oA.x = fmaxf(C[NI-1][0] + tA.x + m2t.x, 0.f);
      oA.y = fmaxf(C[NI-1][1] + tA.y + m2t.y, 0.f);
      oB.x = fmaxf(C[NI-1][2] + tB.x + m2t.x, 0.f);
      oB.y = fmaxf(C[NI-1][3] + tB.y + m2t.y, 0.f);
      *(float2*)(triOut + (base + wrow + g)*TT + tc)     = oA;
      *(float2*)(triOut + (base + wrow + 8 + g)*TT + tc) = oB;
    }
  }
}

template<int NI, int NBASE, bool TRI>
__device__ __forceinline__ void flush_rm(const float rm[9][4], bool anyM0, bool anyM1,
  int b, int r0, int wrow, int g, int tg4)
{
  const int NM = TRI ? (NI - 1) : NI;
  size_t rowA = (size_t)(b*NN + r0 + wrow + g);
  const float* M1a = g_m1 + rowA*DD;
  const float* M1b = M1a + 8*DD;
  unsigned* Ga = g_msgs + rowA*DD;
  unsigned* Gb = Ga + 8*DD;
  #pragma unroll
  for (int ni = 0; ni < NM; ni++){
    int n = NBASE + 8*ni + 2*tg4;
    float2 m1A = *(const float2*)(M1a + n);
    float2 m1B = *(const float2*)(M1b + n);
    float v0 = rm[ni][0] + m1A.x, v1 = rm[ni][1] + m1A.y;
    float v2 = rm[ni][2] + m1B.x, v3 = rm[ni][3] + m1B.y;
    if (anyM0){ v0 = fmaxf(v0, 0.f); v1 = fmaxf(v1, 0.f); }
    if (anyM1){ v2 = fmaxf(v2, 0.f); v3 = fmaxf(v3, 0.f); }
    atomicMax(Ga + n,     enc_f(v0));
    atomicMax(Ga + n + 1, enc_f(v1));
    atomicMax(Gb + n,     enc_f(v2));
    atomicMax(Gb + n + 1, enc_f(v3));
  }
}

__global__ void __launch_bounds__(256, 1) k_main(
  const float* __restrict__ edge, const float* __restrict__ adj,
  const float* __restrict__ Wme, const float* __restrict__ Wte,
  float* __restrict__ triOut)
{
  extern __shared__ float smf[];
  const int tid = threadIdx.x;
  const int b   = blockIdx.z;
  const int r0  = blockIdx.x * RB;
  const int s0  = blockIdx.y * SC;

  // kick off first A-tile prefetch before staging weights
  prefetch_step(smf, edge, adj, b, r0, s0, 0, tid);
  CP_COMMIT();

  // stage W as (k,k+4) float2 pairs, tf32-rounded; row stride WSTR float2
  for (int idx = tid; idx < 64*NTOT; idx += 256){
    int kk = idx / NTOT, n = idx - kk*NTOT;
    int klo = (kk >> 2)*8 + (kk & 3), khi = klo + 4;
    float lo = (n < DD) ? Wme[klo*DD + n] : Wte[klo*TT + (n - DD)];
    float hi = (n < DD) ? Wme[khi*DD + n] : Wte[khi*TT + (n - DD)];
    ((float2*)(smf + OFF_W2))[kk*WSTR + n] = make_float2(to_tf32(lo), to_tf32(hi));
  }
  // stage receiver-side t1
  for (int idx = tid; idx < RB*TT; idx += 256)
    smf[OFF_T1 + idx] = g_t1[(size_t)(b*NN + r0)*TT + idx];

  const int w = tid >> 5, lane = tid & 31;
  const int g = lane >> 2, tg4 = lane & 3;
  const int wrow = (w & 3) << 4;
  const bool loW = (w < 4);

  float rm[9][4];
  const float NEG = __int_as_float(0xff800000);
  #pragma unroll
  for (int i = 0; i < 9; i++){ rm[i][0]=NEG; rm[i][1]=NEG; rm[i][2]=NEG; rm[i][3]=NEG; }
  bool anyM0 = false, anyM1 = false;

  for (int step = 0; step < 16; step++){
    int buf = step & 1;
    if (step < 15){
      prefetch_step(smf, edge, adj, b, r0, s0 + (step + 1)*2, buf ^ 1, tid);
      CP_COMMIT();
      CP_WAIT1();
    } else {
      CP_WAIT0();
    }
    __syncthreads();
    if (loW)
      step_compute<9, 0,  false>(smf, buf, wrow, g, tg4, rm, anyM0, anyM1,
                                 b, r0, s0 + step*2, triOut);
    else
      step_compute<8, 72, true >(smf, buf, wrow, g, tg4, rm, anyM0, anyM1,
                                 b, r0, s0 + step*2, triOut);
    __syncthreads();
  }

  if (loW) flush_rm<9, 0,  false>(rm, anyM0, anyM1, b, r0, wrow, g, tg4);
  else     flush_rm<8, 72, true >(rm, anyM0, anyM1, b, r0, wrow, g, tg4);
}

// -------- K3: ret = o1full + msgs @ Wo2, tiled 16 nodes/block --------
__global__ void __launch_bounds__(256) k_out(
  const float* __restrict__ Wo2, float* __restrict__ ret)
{
  __shared__ float mz[16][128];        // 8 KB
  __shared__ float red[2][16][128];    // 16 KB
  const int nb0 = blockIdx.x * 16;
  const int tid = threadIdx.x;
  for (int idx = tid; idx < 16*128; idx += 256){
    int i = idx >> 7, h = idx & 127;
    mz[i][h] = dec_f(g_msgs[(size_t)(nb0 + i)*DD + h]);
  }
  __syncthreads();
  const int d = tid & 127, hv = tid >> 7;
  float acc[16];
  #pragma unroll
  for (int i = 0; i < 16; i++) acc[i] = 0.f;
  const int h0 = hv * 64;
  for (int hh = 0; hh < 64; hh++){
    int h = h0 + hh;
    float wv = Wo2[h*DD + d];
    #pragma unroll
    for (int i = 0; i < 16; i++) acc[i] += mz[i][h] * wv;
  }
  #pragma unroll
  for (int i = 0; i < 16; i++) red[hv][i][d] = acc[i];
  __syncthreads();
  for (int idx = tid; idx < 16*128; idx += 256){
    int i = idx >> 7, dd = idx & 127;
    int bi = nb0 + i;
    ret[(size_t)bi*DD + dd] = g_o1[(size_t)bi*DD + dd]
                            + red[0][i][dd] + red[1][i][dd];
  }
}

// -------- launcher --------
extern "C" void kernel_launch(void* const* d_in, const int* in_sizes, int n_in,
                              void* d_out, int out_size){
  const float* node   = (const float*)d_in[0];
  const float* edge   = (const float*)d_in[1];
  const float* graph  = (const float*)d_in[2];
  const float* adjm   = (const float*)d_in[3];
  const float* hidden = (const float*)d_in[4];
  const float* Wm1 = (const float*)d_in[5];  const float* bm1 = (const float*)d_in[6];
  const float* Wm2 = (const float*)d_in[7];  const float* bm2 = (const float*)d_in[8];
  const float* Wme = (const float*)d_in[9];  const float* bme = (const float*)d_in[10];
  const float* Wmg = (const float*)d_in[11]; const float* bmg = (const float*)d_in[12];
  const float* Wo1 = (const float*)d_in[13]; const float* bo1 = (const float*)d_in[14];
  const float* Wo2 = (const float*)d_in[15]; const float* bo2 = (const float*)d_in[16];
  const float* Wt1 = (const float*)d_in[17]; const float* bt1 = (const float*)d_in[18];
  const float* Wt2 = (const float*)d_in[19]; const float* bt2 = (const float*)d_in[20];
  const float* Wte = (const float*)d_in[21]; const float* bte = (const float*)d_in[22];
  const float* Wtg = (const float*)d_in[23]; const float* btg = (const float*)d_in[24];

  float* ret = (float*)d_out;                 // [2,512,128]
  float* tri = ret + (size_t)BB*NN*DD;        // [2,512,512,8]

  cudaFuncSetAttribute(k_main, cudaFuncAttributeMaxDynamicSharedMemorySize, SMEM_BYTES);

  k_pre0<<<1, 256>>>(graph, Wmg, bm1, bm2, bme, bmg, Wtg, bt1, bt2, bte, btg);
  k_pre1<<<BB*NN/8, 256>>>(node, hidden, Wm1, Wm2, Wo1, Wt1, Wt2, bo1, bo2);
  k_init_msgs<<<(BB*NN*DD)/256, 256>>>();
  k_main<<<dim3(NN/RB, NN/SC, BB), 256, SMEM_BYTES>>>(edge, adjm, Wme, Wte, tri);
  k_out<<<BB*NN/16, 256>>>(Wo2, ret);
}

// round 8
// speedup vs baseline: 1.2981x; 1.0056x over previous
#include <cuda_runtime.h>
#include <cstdint>
#include <cstddef>

#define BB 2
#define NN 512
#define HH 128
#define DD 128
#define TT 8
#define ZZ 256
#define NTOT 136

// -------- device scratch --------
__device__ float g_m1[BB*NN*DD];   // z@Wm1 + (all msg biases) + graph@Wmg  [receiver]
__device__ float g_m2[BB*NN*DD];   // z@Wm2                                 [sender]
__device__ float g_o1[BB*NN*DD];   // z@Wo1 + bo1 + bo2
__device__ float g_t1[BB*NN*TT];   // z@Wt1 + (all tri biases) + graph@Wtg  [receiver]
__device__ float g_t2[BB*NN*TT];   // z@Wt2                                 [sender]
__device__ float g_mg[BB*DD];
__device__ float g_tg[BB*TT];
__device__ unsigned g_msgs[BB*NN*DD]; // encoded-float running max

__device__ __forceinline__ float to_tf32(float x){
  unsigned u; asm("cvt.rna.tf32.f32 %0, %1;" : "=r"(u) : "f"(x));
  return __uint_as_float(u);
}
__device__ __forceinline__ unsigned enc_f(float f){
  unsigned u = __float_as_uint(f);
  return (u & 0x80000000u) ? ~u : (u | 0x80000000u);
}
__device__ __forceinline__ float dec_f(unsigned k){
  unsigned u = (k & 0x80000000u) ? (k & 0x7fffffffu) : ~k;
  return __uint_as_float(u);
}
__device__ __forceinline__ void mma8(float c[4], float a0,float a1,float a2,float a3,
                                     float b0, float b1){
  asm volatile("mma.sync.aligned.m16n8k8.row.col.f32.tf32.tf32.f32 "
      "{%0,%1,%2,%3}, {%4,%5,%6,%7}, {%8,%9}, {%0,%1,%2,%3};\n"
      : "+f"(c[0]), "+f"(c[1]), "+f"(c[2]), "+f"(c[3])
      : "r"(__float_as_uint(a0)), "r"(__float_as_uint(a1)),
        "r"(__float_as_uint(a2)), "r"(__float_as_uint(a3)),
        "r"(__float_as_uint(b0)), "r"(__float_as_uint(b1)));
}
__device__ __forceinline__ void cp16(void* smem, const void* gmem){
  unsigned s = (unsigned)__cvta_generic_to_shared(smem);
  asm volatile("cp.async.cg.shared.global [%0], [%1], 16;\n" :: "r"(s), "l"(gmem));
}
#define CP_COMMIT() asm volatile("cp.async.commit_group;\n" ::: "memory")
#define CP_WAIT1()  asm volatile("cp.async.wait_group 1;\n" ::: "memory")
#define CP_WAIT0()  asm volatile("cp.async.wait_group 0;\n" ::: "memory")

// -------- K0: graph terms + bias folding --------
__global__ void k_pre0(const float* __restrict__ graph,
  const float* __restrict__ Wmg, const float* __restrict__ bm1, const float* __restrict__ bm2,
  const float* __restrict__ bme, const float* __restrict__ bmg,
  const float* __restrict__ Wtg, const float* __restrict__ bt1, const float* __restrict__ bt2,
  const float* __restrict__ bte, const float* __restrict__ btg)
{
  int t = threadIdx.x;            // 256 threads
  int b = t >> 7, d = t & 127;
  float s = bm1[d] + bm2[d] + bme[d] + bmg[d];
  for (int h = 0; h < HH; h++) s += graph[b*HH + h] * Wmg[h*DD + d];
  g_mg[t] = s;
  if (t < BB*TT){
    int bb = t >> 3, tt = t & 7;
    float s2 = bt1[tt] + bt2[tt] + bte[tt] + btg[tt];
    for (int h = 0; h < HH; h++) s2 += graph[bb*HH + h] * Wtg[h*TT + tt];
    g_tg[t] = s2;
  }
}

// -------- K1: per-node precompute, tiled (8 nodes/block, h split in halves) ----
__global__ void __launch_bounds__(256) k_pre1(
  const float* __restrict__ node, const float* __restrict__ hidden,
  const float* __restrict__ Wm1, const float* __restrict__ Wm2, const float* __restrict__ Wo1,
  const float* __restrict__ Wt1, const float* __restrict__ Wt2,
  const float* __restrict__ bo1, const float* __restrict__ bo2)
{
  __shared__ float z[8][256];          // 8 KB
  __shared__ float red[2][3][8][128];  // 24 KB
  const int nb0 = blockIdx.x * 8;
  const int tid = threadIdx.x;
  for (int idx = tid; idx < 8*256; idx += 256){
    int i = idx >> 8, h = idx & 255;
    int bi = nb0 + i;
    z[i][h] = (h < HH) ? node[bi*HH + h] : hidden[bi*HH + (h - HH)];
  }
  __syncthreads();
  const int d = tid & 127, hv = tid >> 7;
  float a1[8], a2[8], a3[8];
  #pragma unroll
  for (int i = 0; i < 8; i++){ a1[i]=0.f; a2[i]=0.f; a3[i]=0.f; }
  const int h0 = hv * 128;
  for (int hh = 0; hh < 128; hh++){
    int h = h0 + hh;
    float w1 = Wm1[h*DD + d], w2 = Wm2[h*DD + d], w3 = Wo1[h*DD + d];
    #pragma unroll
    for (int i = 0; i < 8; i++){
      float zv = z[i][h];
      a1[i] += zv * w1; a2[i] += zv * w2; a3[i] += zv * w3;
    }
  }
  #pragma unroll
  for (int i = 0; i < 8; i++){
    red[hv][0][i][d] = a1[i]; red[hv][1][i][d] = a2[i]; red[hv][2][i][d] = a3[i];
  }
  __syncthreads();
  for (int idx = tid; idx < 1024; idx += 256){
    int i = idx >> 7, dd = idx & 127;
    int bi = nb0 + i, b = bi >> 9;
    float v1 = red[0][0][i][dd] + red[1][0][i][dd];
    float v2 = red[0][1][i][dd] + red[1][1][i][dd];
    float v3 = red[0][2][i][dd] + red[1][2][i][dd];
    g_m1[(size_t)bi*DD + dd] = v1 + g_mg[b*DD + dd];
    g_m2[(size_t)bi*DD + dd] = v2;
    g_o1[(size_t)bi*DD + dd] = v3 + bo1[dd] + bo2[dd];
  }
  if (tid < 128){
    int i = tid >> 4, t = (tid >> 1) & 7, m = tid & 1;
    const float* W = m ? Wt2 : Wt1;
    float s = 0.f;
    for (int h = 0; h < ZZ; h++) s += z[i][h] * W[h*TT + t];
    int bi = nb0 + i, b = bi >> 9;
    if (m == 0) g_t1[(size_t)bi*TT + t] = s + g_tg[b*TT + t];
    else        g_t2[(size_t)bi*TT + t] = s;
  }
}

__global__ void k_init_msgs(){
  int i = blockIdx.x * 256 + threadIdx.x;
  g_msgs[i] = 0x007fffffu;   // enc(-inf)
}

// -------- K2: main fused edge GEMM + triplet relu + masked max --------
#define RB 64
#define SC 32
#define WSTR 136                  // W2 row stride in float2 (NO overflow; uniform degree-2 banks)
// smem layout (float offsets)
#define OFF_W2   0                      // 64 rows x 136 float2 = 17408 floats
#define OFF_A    (64*WSTR*2)            // 17408: 2 bufs x 2 senders x 64x132
#define OFF_M2   (OFF_A + 2*2*64*132)   // 51200: 2 bufs x 2 x 136
#define OFF_ADJ  (OFF_M2 + 2*2*136)     // 51744: 2 bufs x 2 x 64
#define OFF_T1   (OFF_ADJ + 2*2*64)     // 52000: 64 x 8
#define SMEM_WORDS (OFF_T1 + 64*8)      // 52512
#define SMEM_BYTES (SMEM_WORDS*4)       // 210048

__device__ __forceinline__ void prefetch_step(float* smf, const float* edge,
  const float* adj, int b, int r0, int sbase, int buf, int tid)
{
  float* Ab = smf + OFF_A + buf*(2*64*132);
  #pragma unroll
  for (int i = 0; i < 16; i++){
    int idx = i*256 + tid;
    int jj = i >> 3;                 // sender within pair
    int s  = sbase + jj;
    int r  = (idx >> 5) & 63;
    int c  = idx & 31;
    const float* gp = edge + ((size_t)(b*NN + s)*NN + r0 + r)*HH + c*4;
    cp16(Ab + jj*(64*132) + r*132 + c*4, gp);
  }
  if (tid < 64){
    int jj = tid >> 5, c = tid & 31;
    int s = sbase + jj;
    cp16(smf + OFF_M2 + buf*272 + jj*136 + c*4, g_m2 + (size_t)(b*NN + s)*DD + c*4);
  } else if (tid < 68){
    int q = tid - 64; int jj = q >> 1, c = q & 1;
    int s = sbase + jj;
    cp16(smf + OFF_M2 + buf*272 + jj*136 + 128 + c*4, g_t2 + (size_t)(b*NN + s)*TT + c*4);
  } else if (tid < 100){
    int q = tid - 68; int jj = q >> 4, c = q & 15;
    int s = sbase + jj;
    cp16(smf + OFF_ADJ + buf*128 + jj*64 + c*4, adj + (size_t)(b*NN + s)*NN + r0 + c*4);
  }
}

template<int NI, int NBASE, bool TRI>
__device__ __forceinline__ void step_compute(
  const float* __restrict__ smf, int buf, int wrow, int g, int tg4,
  float rm[9][4], bool& anyM0, bool& anyM1,
  int b, int r0, int sstep, float* __restrict__ triOut)
{
  const float* A0 = smf + OFF_A + buf*(2*64*132) + (wrow + g)*132 + tg4;
  const float* A1 = A0 + 64*132;
  const float2* Wp = (const float2*)smf + (size_t)tg4*WSTR + NBASE + g;

  float C0[NI][4], C1[NI][4];
  #pragma unroll
  for (int i = 0; i < NI; i++){
    C0[i][0]=0.f; C0[i][1]=0.f; C0[i][2]=0.f; C0[i][3]=0.f;
    C1[i][0]=0.f; C1[i][1]=0.f; C1[i][2]=0.f; C1[i][3]=0.f;
  }

  #pragma unroll 4
  for (int ks = 0; ks < 16; ks++){
    const float* a0 = A0 + ks*8;
    float x0 = to_tf32(a0[0]), x1 = to_tf32(a0[8*132]);
    float x2 = to_tf32(a0[4]), x3 = to_tf32(a0[8*132 + 4]);
    const float* a1 = A1 + ks*8;
    float y0 = to_tf32(a1[0]), y1 = to_tf32(a1[8*132]);
    float y2 = to_tf32(a1[4]), y3 = to_tf32(a1[8*132 + 4]);
    const float2* wp = Wp + ks*4*WSTR;
    #pragma unroll
    for (int ni = 0; ni < NI; ni++){
      float2 bb = wp[ni*8];
      mma8(C0[ni], x0,x1,x2,x3, bb.x, bb.y);
      mma8(C1[ni], y0,y1,y2,y3, bb.x, bb.y);
    }
  }

  #pragma unroll
  for (int j = 0; j < 2; j++){
    const float* M2 = smf + OFF_M2 + buf*272 + j*136;
    const float* AD = smf + OFF_ADJ + buf*128 + j*64;
    float adjA = AD[wrow + g];
    float adjB = AD[wrow + 8 + g];
    if (adjA == 0.f) anyM0 = true;
    if (adjB == 0.f) anyM1 = true;
    const float (*C)[4] = j ? C1 : C0;
    const int NM = TRI ? (NI - 1) : NI;
    #pragma unroll
    for (int ni = 0; ni < NM; ni++){
      int n = NBASE + 8*ni + 2*tg4;
      float2 m2 = *(const float2*)(M2 + n);
      if (adjA != 0.f){
        rm[ni][0] = fmaxf(rm[ni][0], C[ni][0] + m2.x);
        rm[ni][1] = fmaxf(rm[ni][1], C[ni][1] + m2.y);
      }
      if (adjB != 0.f){
        rm[ni][2] = fmaxf(rm[ni][2], C[ni][2] + m2.x);
        rm[ni][3] = fmaxf(rm[ni][3], C[ni][3] + m2.y);
      }
    }
    if (TRI){
      int tc = 2*tg4;
      float2 m2t = *(const float2*)(M2 + 128 + tc);
      const float* T1 = smf + OFF_T1;
      float2 tA = *(const float2*)(T1 + (wrow + g)*TT + tc);
      float2 tB = *(const float2*)(T1 + (wrow + 8 + g)*TT + tc);
      int s = sstep + j;
      size_t base = (size_t)(b*NN + s)*NN + r0;
      float2 oA, oB;
      oA.x = fmaxf(C[NI-1][0] + tA.x + m2t.x, 0.f);
      oA.y = fmaxf(C[NI-1][1] + tA.y + m2t.y, 0.f);
      oB.x = fmaxf(C[NI-1][2] + tB.x + m2t.x, 0.f);
      oB.y = fmaxf(C[NI-1][3] + tB.y + m2t.y, 0.f);
      *(float2*)(triOut + (base + wrow + g)*TT + tc)     = oA;
      *(float2*)(triOut + (base + wrow + 8 + g)*TT + tc) = oB;
    }
  }
}

template<int NI, int NBASE, bool TRI>
__device__ __forceinline__ void flush_rm(const float rm[9][4], bool anyM0, bool anyM1,
  int b, int r0, int wrow, int g, int tg4)
{
  const int NM = TRI ? (NI - 1) : NI;
  size_t rowA = (size_t)(b*NN + r0 + wrow + g);
  const float* M1a = g_m1 + rowA*DD;
  const float* M1b = M1a + 8*DD;
  unsigned* Ga = g_msgs + rowA*DD;
  unsigned* Gb = Ga + 8*DD;
  #pragma unroll
  for (int ni = 0; ni < NM; ni++){
    int n = NBASE + 8*ni + 2*tg4;
    float2 m1A = *(const float2*)(M1a + n);
    float2 m1B = *(const float2*)(M1b + n);
    float v0 = rm[ni][0] + m1A.x, v1 = rm[ni][1] + m1A.y;
    float v2 = rm[ni][2] + m1B.x, v3 = rm[ni][3] + m1B.y;
    if (anyM0){ v0 = fmaxf(v0, 0.f); v1 = fmaxf(v1, 0.f); }
    if (anyM1){ v2 = fmaxf(v2, 0.f); v3 = fmaxf(v3, 0.f); }
    atomicMax(Ga + n,     enc_f(v0));
    atomicMax(Ga + n + 1, enc_f(v1));
    atomicMax(Gb + n,     enc_f(v2));
    atomicMax(Gb + n + 1, enc_f(v3));
  }
}

__global__ void __launch_bounds__(256, 1) k_main(
  const float* __restrict__ edge, const float* __restrict__ adj,
  const float* __restrict__ Wme, const float* __restrict__ Wte,
  float* __restrict__ triOut)
{
  extern __shared__ float smf[];
  const int tid = threadIdx.x;
  const int b   = blockIdx.z;
  const int r0  = blockIdx.x * RB;
  const int s0  = blockIdx.y * SC;

  // kick off first A-tile prefetch before staging weights
  prefetch_step(smf, edge, adj, b, r0, s0, 0, tid);
  CP_COMMIT();

  // stage W as (k,k+4) float2 pairs, tf32-rounded; row stride WSTR float2
  for (int idx = tid; idx < 64*NTOT; idx += 256){
    int kk = idx / NTOT, n = idx - kk*NTOT;
    int klo = (kk >> 2)*8 + (kk & 3), khi = klo + 4;
    float lo = (n < DD) ? Wme[klo*DD + n] : Wte[klo*TT + (n - DD)];
    float hi = (n < DD) ? Wme[khi*DD + n] : Wte[khi*TT + (n - DD)];
    ((float2*)(smf + OFF_W2))[kk*WSTR + n] = make_float2(to_tf32(lo), to_tf32(hi));
  }
  // stage receiver-side t1
  for (int idx = tid; idx < RB*TT; idx += 256)
    smf[OFF_T1 + idx] = g_t1[(size_t)(b*NN + r0)*TT + idx];

  const int w = tid >> 5, lane = tid & 31;
  const int g = lane >> 2, tg4 = lane & 3;
  const int wrow = (w & 3) << 4;
  const bool loW = (w < 4);

  float rm[9][4];
  const float NEG = __int_as_float(0xff800000);
  #pragma unroll
  for (int i = 0; i < 9; i++){ rm[i][0]=NEG; rm[i][1]=NEG; rm[i][2]=NEG; rm[i][3]=NEG; }
  bool anyM0 = false, anyM1 = false;

  for (int step = 0; step < 16; step++){
    int buf = step & 1;
    if (step < 15){
      prefetch_step(smf, edge, adj, b, r0, s0 + (step + 1)*2, buf ^ 1, tid);
      CP_COMMIT();
      CP_WAIT1();
    } else {
      CP_WAIT0();
    }
    __syncthreads();
    if (loW)
      step_compute<9, 0,  false>(smf, buf, wrow, g, tg4, rm, anyM0, anyM1,
                                 b, r0, s0 + step*2, triOut);
    else
      step_compute<8, 72, true >(smf, buf, wrow, g, tg4, rm, anyM0, anyM1,
                                 b, r0, s0 + step*2, triOut);
    __syncthreads();
  }

  if (loW) flush_rm<9, 0,  false>(rm, anyM0, anyM1, b, r0, wrow, g, tg4);
  else     flush_rm<8, 72, true >(rm, anyM0, anyM1, b, r0, wrow, g, tg4);
}

// -------- K3: ret = o1full + msgs @ Wo2, tiled 16 nodes/block --------
__global__ void __launch_bounds__(256) k_out(
  const float* __restrict__ Wo2, float* __restrict__ ret)
{
  __shared__ float mz[16][128];        // 8 KB
  __shared__ float red[2][16][128];    // 16 KB
  const int nb0 = blockIdx.x * 16;
  const int tid = threadIdx.x;
  for (int idx = tid; idx < 16*128; idx += 256){
    int i = idx >> 7, h = idx & 127;
    mz[i][h] = dec_f(g_msgs[(size_t)(nb0 + i)*DD + h]);
  }
  __syncthreads();
  const int d = tid & 127, hv = tid >> 7;
  float acc[16];
  #pragma unroll
  for (int i = 0; i < 16; i++) acc[i] = 0.f;
  const int h0 = hv * 64;
  for (int hh = 0; hh < 64; hh++){
    int h = h0 + hh;
    float wv = Wo2[h*DD + d];
    #pragma unroll
    for (int i = 0; i < 16; i++) acc[i] += mz[i][h] * wv;
  }
  #pragma unroll
  for (int i = 0; i < 16; i++) red[hv][i][d] = acc[i];
  __syncthreads();
  for (int idx = tid; idx < 16*128; idx += 256){
    int i = idx >> 7, dd = idx & 127;
    int bi = nb0 + i;
    ret[(size_t)bi*DD + dd] = g_o1[(size_t)bi*DD + dd]
                            + red[0][i][dd] + red[1][i][dd];
  }
}

// -------- launcher --------
extern "C" void kernel_launch(void* const* d_in, const int* in_sizes, int n_in,
                              void* d_out, int out_size){
  const float* node   = (const float*)d_in[0];
  const float* edge   = (const float*)d_in[1];
  const float* graph  = (const float*)d_in[2];
  const float* adjm   = (const float*)d_in[3];
  const float* hidden = (const float*)d_in[4];
  const float* Wm1 = (const float*)d_in[5];  const float* bm1 = (const float*)d_in[6];
  const float* Wm2 = (const float*)d_in[7];  const float* bm2 = (const float*)d_in[8];
  const float* Wme = (const float*)d_in[9];  const float* bme = (const float*)d_in[10];
  const float* Wmg = (const float*)d_in[11]; const float* bmg = (const float*)d_in[12];
  const float* Wo1 = (const float*)d_in[13]; const float* bo1 = (const float*)d_in[14];
  const float* Wo2 = (const float*)d_in[15]; const float* bo2 = (const float*)d_in[16];
  const float* Wt1 = (const float*)d_in[17]; const float* bt1 = (const float*)d_in[18];
  const float* Wt2 = (const float*)d_in[19]; const float* bt2 = (const float*)d_in[20];
  const float* Wte = (const float*)d_in[21]; const float* bte = (const float*)d_in[22];
  const float* Wtg = (const float*)d_in[23]; const float* btg = (const float*)d_in[24];

  float* ret = (float*)d_out;                 // [2,512,128]
  float* tri = ret + (size_t)BB*NN*DD;        // [2,512,512,8]

  cudaFuncSetAttribute(k_main, cudaFuncAttributeMaxDynamicSharedMemorySize, SMEM_BYTES);

  k_pre0<<<1, 256>>>(graph, Wmg, bm1, bm2, bme, bmg, Wtg, bt1, bt2, bte, btg);
  k_pre1<<<BB*NN/8, 256>>>(node, hidden, Wm1, Wm2, Wo1, Wt1, Wt2, bo1, bo2);
  k_init_msgs<<<(BB*NN*DD)/256, 256>>>();
  k_main<<<dim3(NN/RB, NN/SC, BB), 256, SMEM_BYTES>>>(edge, adjm, Wme, Wte, tri);
  k_out<<<BB*NN/16, 256>>>(Wo2, ret);
}

// round 14
// speedup vs baseline: 1.4726x; 1.1344x over previous
#include <cuda_runtime.h>
#include <cstdint>
#include <cstddef>

#define BB 2
#define NN 512
#define HH 128
#define DD 128
#define TT 8
#define ZZ 256
#define NTOT 136

// -------- device scratch --------
__device__ float g_m1[BB*NN*DD];   // z@Wm1 + (all msg biases) + graph@Wmg  [receiver]
__device__ float g_m2[BB*NN*DD];   // z@Wm2                                 [sender]
__device__ float g_o1[BB*NN*DD];   // z@Wo1 + bo1 + bo2
__device__ float g_t1[BB*NN*TT];   // z@Wt1 + (all tri biases) + graph@Wtg  [receiver]
__device__ float g_t2[BB*NN*TT];   // z@Wt2                                 [sender]
__device__ float g_mg[BB*DD];
__device__ float g_tg[BB*TT];
__device__ unsigned g_msgs[BB*NN*DD]; // encoded-float running max

__device__ __forceinline__ float to_tf32(float x){
  unsigned u; asm("cvt.rna.tf32.f32 %0, %1;" : "=r"(u) : "f"(x));
  return __uint_as_float(u);
}
__device__ __forceinline__ unsigned enc_f(float f){
  unsigned u = __float_as_uint(f);
  return (u & 0x80000000u) ? ~u : (u | 0x80000000u);
}
__device__ __forceinline__ float dec_f(unsigned k){
  unsigned u = (k & 0x80000000u) ? (k & 0x7fffffffu) : ~k;
  return __uint_as_float(u);
}
__device__ __forceinline__ void mma8(float c[4], float a0,float a1,float a2,float a3,
                                     float b0, float b1){
  asm volatile("mma.sync.aligned.m16n8k8.row.col.f32.tf32.tf32.f32 "
      "{%0,%1,%2,%3}, {%4,%5,%6,%7}, {%8,%9}, {%0,%1,%2,%3};\n"
      : "+f"(c[0]), "+f"(c[1]), "+f"(c[2]), "+f"(c[3])
      : "r"(__float_as_uint(a0)), "r"(__float_as_uint(a1)),
        "r"(__float_as_uint(a2)), "r"(__float_as_uint(a3)),
        "r"(__float_as_uint(b0)), "r"(__float_as_uint(b1)));
}
__device__ __forceinline__ void cp16(void* smem, const void* gmem){
  unsigned s = (unsigned)__cvta_generic_to_shared(smem);
  asm volatile("cp.async.cg.shared.global [%0], [%1], 16;\n" :: "r"(s), "l"(gmem));
}
#define CP_COMMIT() asm volatile("cp.async.commit_group;\n" ::: "memory")
#define CP_WAIT1()  asm volatile("cp.async.wait_group 1;\n" ::: "memory")
#define CP_WAIT0()  asm volatile("cp.async.wait_group 0;\n" ::: "memory")

// -------- K0: graph terms + bias folding --------
__global__ void k_pre0(const float* __restrict__ graph,
  const float* __restrict__ Wmg, const float* __restrict__ bm1, const float* __restrict__ bm2,
  const float* __restrict__ bme, const float* __restrict__ bmg,
  const float* __restrict__ Wtg, const float* __restrict__ bt1, const float* __restrict__ bt2,
  const float* __restrict__ bte, const float* __restrict__ btg)
{
  int t = threadIdx.x;
  int b = t >> 7, d = t & 127;
  float s = bm1[d] + bm2[d] + bme[d] + bmg[d];
  for (int h = 0; h < HH; h++) s += graph[b*HH + h] * Wmg[h*DD + d];
  g_mg[t] = s;
  if (t < BB*TT){
    int bb = t >> 3, tt = t & 7;
    float s2 = bt1[tt] + bt2[tt] + bte[tt] + btg[tt];
    for (int h = 0; h < HH; h++) s2 += graph[bb*HH + h] * Wtg[h*TT + tt];
    g_tg[t] = s2;
  }
}

// -------- K1: per-node precompute --------
__global__ void __launch_bounds__(256) k_pre1(
  const float* __restrict__ node, const float* __restrict__ hidden,
  const float* __restrict__ Wm1, const float* __restrict__ Wm2, const float* __restrict__ Wo1,
  const float* __restrict__ Wt1, const float* __restrict__ Wt2,
  const float* __restrict__ bo1, const float* __restrict__ bo2)
{
  __shared__ float z[8][256];
  __shared__ float red[2][3][8][128];
  const int nb0 = blockIdx.x * 8;
  const int tid = threadIdx.x;
  for (int idx = tid; idx < 8*256; idx += 256){
    int i = idx >> 8, h = idx & 255;
    int bi = nb0 + i;
    z[i][h] = (h < HH) ? node[bi*HH + h] : hidden[bi*HH + (h - HH)];
  }
  __syncthreads();
  const int d = tid & 127, hv = tid >> 7;
  float a1[8], a2[8], a3[8];
  #pragma unroll
  for (int i = 0; i < 8; i++){ a1[i]=0.f; a2[i]=0.f; a3[i]=0.f; }
  const int h0 = hv * 128;
  for (int hh = 0; hh < 128; hh++){
    int h = h0 + hh;
    float w1 = Wm1[h*DD + d], w2 = Wm2[h*DD + d], w3 = Wo1[h*DD + d];
    #pragma unroll
    for (int i = 0; i < 8; i++){
      float zv = z[i][h];
      a1[i] += zv * w1; a2[i] += zv * w2; a3[i] += zv * w3;
    }
  }
  #pragma unroll
  for (int i = 0; i < 8; i++){
    red[hv][0][i][d] = a1[i]; red[hv][1][i][d] = a2[i]; red[hv][2][i][d] = a3[i];
  }
  __syncthreads();
  for (int idx = tid; idx < 1024; idx += 256){
    int i = idx >> 7, dd = idx & 127;
    int bi = nb0 + i, b = bi >> 9;
    float v1 = red[0][0][i][dd] + red[1][0][i][dd];
    float v2 = red[0][1][i][dd] + red[1][1][i][dd];
    float v3 = red[0][2][i][dd] + red[1][2][i][dd];
    g_m1[(size_t)bi*DD + dd] = v1 + g_mg[b*DD + dd];
    g_m2[(size_t)bi*DD + dd] = v2;
    g_o1[(size_t)bi*DD + dd] = v3 + bo1[dd] + bo2[dd];
  }
  if (tid < 128){
    int i = tid >> 4, t = (tid >> 1) & 7, m = tid & 1;
    const float* W = m ? Wt2 : Wt1;
    float s = 0.f;
    for (int h = 0; h < ZZ; h++) s += z[i][h] * W[h*TT + t];
    int bi = nb0 + i, b = bi >> 9;
    if (m == 0) g_t1[(size_t)bi*TT + t] = s + g_tg[b*TT + t];
    else        g_t2[(size_t)bi*TT + t] = s;
  }
}

__global__ void k_init_msgs(){
  int i = blockIdx.x * 256 + threadIdx.x;
  g_msgs[i] = 0x007fffffu;   // enc(-inf)
}

// -------- K2: main fused edge GEMM + triplet relu + masked max --------
// 384 threads = 12 warps: 4 row-groups (16 rows each) x 3 col-groups (tiles 6/6/5)
#define RB 64
#define SC 64
#define NTHR 384
#define WT_STR 68                 // transposed W row stride in float2 (conflict-free)
// smem layout (float offsets)
#define OFF_W2   0                          // 136 n-rows x 68 float2 = 18496 floats
#define OFF_A    (NTOT*WT_STR*2)            // 18496: 2 bufs x 2 senders x 64x132
#define OFF_M2   (OFF_A + 2*2*64*132)       // 52288: 2 bufs x 2 x 136
#define OFF_ADJ  (OFF_M2 + 2*2*136)         // 52832: 2 bufs x 2 x 64
#define OFF_T1   (OFF_ADJ + 2*2*64)         // 53088: 64 x 8
#define SMEM_WORDS (OFF_T1 + 64*8)          // 53600
#define SMEM_BYTES (SMEM_WORDS*4)           // 214400

__device__ __forceinline__ void prefetch_step(float* smf, const float* edge,
  const float* adj, int b, int r0, int sbase, int buf, int tid)
{
  float* Ab = smf + OFF_A + buf*(2*64*132);
  for (int i = tid; i < 4096; i += NTHR){
    int jj = i >> 11;                // sender within pair (2048 float4 each)
    int s  = sbase + jj;
    int r  = (i >> 5) & 63;
    int c  = i & 31;
    const float* gp = edge + ((size_t)(b*NN + s)*NN + r0 + r)*HH + c*4;
    cp16(Ab + jj*(64*132) + r*132 + c*4, gp);
  }
  if (tid < 64){
    int jj = tid >> 5, c = tid & 31;
    int s = sbase + jj;
    cp16(smf + OFF_M2 + buf*272 + jj*136 + c*4, g_m2 + (size_t)(b*NN + s)*DD + c*4);
  } else if (tid < 68){
    int q = tid - 64; int jj = q >> 1, c = q & 1;
    int s = sbase + jj;
    cp16(smf + OFF_M2 + buf*272 + jj*136 + 128 + c*4, g_t2 + (size_t)(b*NN + s)*TT + c*4);
  } else if (tid < 100){
    int q = tid - 68; int jj = q >> 4, c = q & 15;
    int s = sbase + jj;
    cp16(smf + OFF_ADJ + buf*128 + jj*64 + c*4, adj + (size_t)(b*NN + s)*NN + r0 + c*4);
  }
}

// NI tiles starting at tile TG0; TRI => last tile is the triplet tile (cols 128..135)
template<int NI, int TG0, bool TRI>
__device__ __forceinline__ void step_compute(
  const float* __restrict__ smf, int buf, int wrow, int g, int tg4,
  float rm[][4], bool& anyM0, bool& anyM1,
  int b, int r0, int sstep, float* __restrict__ triOut)
{
  const float* A0 = smf + OFF_A + buf*(2*64*132) + (wrow + g)*132 + tg4;
  const float* A1 = A0 + 64*132;
  // transposed W: float2 index = n*WT_STR + kk, kk = 4*ks + tg4
  const float2* Wp = (const float2*)smf + (size_t)(TG0*8 + g)*WT_STR + tg4;

  float C0[NI][4], C1[NI][4];
  #pragma unroll
  for (int i = 0; i < NI; i++){
    C0[i][0]=0.f; C0[i][1]=0.f; C0[i][2]=0.f; C0[i][3]=0.f;
    C1[i][0]=0.f; C1[i][1]=0.f; C1[i][2]=0.f; C1[i][3]=0.f;
  }

  #pragma unroll 4
  for (int ks = 0; ks < 16; ks++){
    const float* a0 = A0 + ks*8;
    float x0 = to_tf32(a0[0]), x1 = to_tf32(a0[8*132]);
    float x2 = to_tf32(a0[4]), x3 = to_tf32(a0[8*132 + 4]);
    const float* a1 = A1 + ks*8;
    float y0 = to_tf32(a1[0]), y1 = to_tf32(a1[8*132]);
    float y2 = to_tf32(a1[4]), y3 = to_tf32(a1[8*132 + 4]);
    const float2* wp = Wp + ks*4;
    #pragma unroll
    for (int ni = 0; ni < NI; ni++){
      float2 bb = wp[ni*8*WT_STR];
      mma8(C0[ni], x0,x1,x2,x3, bb.x, bb.y);
      mma8(C1[ni], y0,y1,y2,y3, bb.x, bb.y);
    }
  }

  #pragma unroll
  for (int j = 0; j < 2; j++){
    const float* M2 = smf + OFF_M2 + buf*272 + j*136;
    const float* AD = smf + OFF_ADJ + buf*128 + j*64;
    float adjA = AD[wrow + g];
    float adjB = AD[wrow + 8 + g];
    if (adjA == 0.f) anyM0 = true;
    if (adjB == 0.f) anyM1 = true;
    const float (*C)[4] = j ? C1 : C0;
    const int NM = TRI ? (NI - 1) : NI;
    #pragma unroll
    for (int ni = 0; ni < NM; ni++){
      int n = (TG0 + ni)*8 + 2*tg4;
      float2 m2 = *(const float2*)(M2 + n);
      if (adjA != 0.f){
        rm[ni][0] = fmaxf(rm[ni][0], C[ni][0] + m2.x);
        rm[ni][1] = fmaxf(rm[ni][1], C[ni][1] + m2.y);
      }
      if (adjB != 0.f){
        rm[ni][2] = fmaxf(rm[ni][2], C[ni][2] + m2.x);
        rm[ni][3] = fmaxf(rm[ni][3], C[ni][3] + m2.y);
      }
    }
    if (TRI){
      int tc = 2*tg4;
      float2 m2t = *(const float2*)(M2 + 128 + tc);
      const float* T1 = smf + OFF_T1;
      float2 tA = *(const float2*)(T1 + (wrow + g)*TT + tc);
      float2 tB = *(const float2*)(T1 + (wrow + 8 + g)*TT + tc);
      int s = sstep + j;
      size_t base = (size_t)(b*NN + s)*NN + r0;
      float2 oA, oB;
      oA.x = fmaxf(C[NI-1][0] + tA.x + m2t.x, 0.f);
      oA.y = fmaxf(C[NI-1][1] + tA.y + m2t.y, 0.f);
      oB.x = fmaxf(C[NI-1][2] + tB.x + m2t.x, 0.f);
      oB.y = fmaxf(C[NI-1][3] + tB.y + m2t.y, 0.f);
      *(float2*)(triOut + (base + wrow + g)*TT + tc)     = oA;
      *(float2*)(triOut + (base + wrow + 8 + g)*TT + tc) = oB;
    }
  }
}

template<int NI, int TG0, bool TRI>
__device__ __forceinline__ void flush_rm(const float rm[][4], bool anyM0, bool anyM1,
  int b, int r0, int wrow, int g, int tg4)
{
  const int NM = TRI ? (NI - 1) : NI;
  size_t rowA = (size_t)(b*NN + r0 + wrow + g);
  const float* M1a = g_m1 + rowA*DD;
  const float* M1b = M1a + 8*DD;
  unsigned* Ga = g_msgs + rowA*DD;
  unsigned* Gb = Ga + 8*DD;
  #pragma unroll
  for (int ni = 0; ni < NM; ni++){
    int n = (TG0 + ni)*8 + 2*tg4;
    float2 m1A = *(const float2*)(M1a + n);
    float2 m1B = *(const float2*)(M1b + n);
    float v0 = rm[ni][0] + m1A.x, v1 = rm[ni][1] + m1A.y;
    float v2 = rm[ni][2] + m1B.x, v3 = rm[ni][3] + m1B.y;
    if (anyM0){ v0 = fmaxf(v0, 0.f); v1 = fmaxf(v1, 0.f); }
    if (anyM1){ v2 = fmaxf(v2, 0.f); v3 = fmaxf(v3, 0.f); }
    atomicMax(Ga + n,     enc_f(v0));
    atomicMax(Ga + n + 1, enc_f(v1));
    atomicMax(Gb + n,     enc_f(v2));
    atomicMax(Gb + n + 1, enc_f(v3));
  }
}

__global__ void __launch_bounds__(NTHR, 1) k_main(
  const float* __restrict__ edge, const float* __restrict__ adj,
  const float* __restrict__ Wme, const float* __restrict__ Wte,
  float* __restrict__ triOut)
{
  extern __shared__ float smf[];
  const int tid = threadIdx.x;
  const int b   = blockIdx.z;
  const int r0  = blockIdx.x * RB;
  const int s0  = blockIdx.y * SC;

  // kick off first A-tile prefetch before staging weights
  prefetch_step(smf, edge, adj, b, r0, s0, 0, tid);
  CP_COMMIT();

  // stage W transposed: [n][kk] float2 (kk packs k=8ks+tg4 and +4), stride 68 float2
  for (int idx = tid; idx < NTOT*64; idx += NTHR){
    int n = idx >> 6, kk = idx & 63;
    int klo = (kk >> 2)*8 + (kk & 3), khi = klo + 4;
    float lo = (n < DD) ? Wme[klo*DD + n] : Wte[klo*TT + (n - DD)];
    float hi = (n < DD) ? Wme[khi*DD + n] : Wte[khi*TT + (n - DD)];
    ((float2*)(smf + OFF_W2))[n*WT_STR + kk] = make_float2(to_tf32(lo), to_tf32(hi));
  }
  // stage receiver-side t1
  for (int idx = tid; idx < RB*TT; idx += NTHR)
    smf[OFF_T1 + idx] = g_t1[(size_t)(b*NN + r0)*TT + idx];

  const int w = tid >> 5, lane = tid & 31;
  const int g = lane >> 2, tg4 = lane & 3;
  const int wrow = (w & 3) << 4;     // row group: 4 groups of 16 rows
  const int cg   = w >> 2;           // col group: 0,1,2

  float rm[6][4];
  const float NEG = __int_as_float(0xff800000);
  #pragma unroll
  for (int i = 0; i < 6; i++){ rm[i][0]=NEG; rm[i][1]=NEG; rm[i][2]=NEG; rm[i][3]=NEG; }
  bool anyM0 = false, anyM1 = false;

  for (int step = 0; step < SC/2; step++){
    int buf = step & 1;
    if (step < SC/2 - 1){
      prefetch_step(smf, edge, adj, b, r0, s0 + (step + 1)*2, buf ^ 1, tid);
      CP_COMMIT();
      CP_WAIT1();
    } else {
      CP_WAIT0();
    }
    __syncthreads();
    if (cg == 0)
      step_compute<6, 0,  false>(smf, buf, wrow, g, tg4, rm, anyM0, anyM1,
                                 b, r0, s0 + step*2, triOut);
    else if (cg == 1)
      step_compute<6, 6,  false>(smf, buf, wrow, g, tg4, rm, anyM0, anyM1,
                                 b, r0, s0 + step*2, triOut);
    else
      step_compute<5, 12, true >(smf, buf, wrow, g, tg4, rm, anyM0, anyM1,
                                 b, r0, s0 + step*2, triOut);
    __syncthreads();
  }

  if (cg == 0)      flush_rm<6, 0,  false>(rm, anyM0, anyM1, b, r0, wrow, g, tg4);
  else if (cg == 1) flush_rm<6, 6,  false>(rm, anyM0, anyM1, b, r0, wrow, g, tg4);
  else              flush_rm<5, 12, true >(rm, anyM0, anyM1, b, r0, wrow, g, tg4);
}

// -------- K3: ret = o1full + msgs @ Wo2 --------
__global__ void __launch_bounds__(256) k_out(
  const float* __restrict__ Wo2, float* __restrict__ ret)
{
  __shared__ float mz[16][128];
  __shared__ float red[2][16][128];
  const int nb0 = blockIdx.x * 16;
  const int tid = threadIdx.x;
  for (int idx = tid; idx < 16*128; idx += 256){
    int i = idx >> 7, h = idx & 127;
    mz[i][h] = dec_f(g_msgs[(size_t)(nb0 + i)*DD + h]);
  }
  __syncthreads();
  const int d = tid & 127, hv = tid >> 7;
  float acc[16];
  #pragma unroll
  for (int i = 0; i < 16; i++) acc[i] = 0.f;
  const int h0 = hv * 64;
  for (int hh = 0; hh < 64; hh++){
    int h = h0 + hh;
    float wv = Wo2[h*DD + d];
    #pragma unroll
    for (int i = 0; i < 16; i++) acc[i] += mz[i][h] * wv;
  }
  #pragma unroll
  for (int i = 0; i < 16; i++) red[hv][i][d] = acc[i];
  __syncthreads();
  for (int idx = tid; idx < 16*128; idx += 256){
    int i = idx >> 7, dd = idx & 127;
    int bi = nb0 + i;
    ret[(size_t)bi*DD + dd] = g_o1[(size_t)bi*DD + dd]
                            + red[0][i][dd] + red[1][i][dd];
  }
}

// -------- launcher --------
extern "C" void kernel_launch(void* const* d_in, const int* in_sizes, int n_in,
                              void* d_out, int out_size){
  const float* node   = (const float*)d_in[0];
  const float* edge   = (const float*)d_in[1];
  const float* graph  = (const float*)d_in[2];
  const float* adjm   = (const float*)d_in[3];
  const float* hidden = (const float*)d_in[4];
  const float* Wm1 = (const float*)d_in[5];  const float* bm1 = (const float*)d_in[6];
  const float* Wm2 = (const float*)d_in[7];  const float* bm2 = (const float*)d_in[8];
  const float* Wme = (const float*)d_in[9];  const float* bme = (const float*)d_in[10];
  const float* Wmg = (const float*)d_in[11]; const float* bmg = (const float*)d_in[12];
  const float* Wo1 = (const float*)d_in[13]; const float* bo1 = (const float*)d_in[14];
  const float* Wo2 = (const float*)d_in[15]; const float* bo2 = (const float*)d_in[16];
  const float* Wt1 = (const float*)d_in[17]; const float* bt1 = (const float*)d_in[18];
  const float* Wt2 = (const float*)d_in[19]; const float* bt2 = (const float*)d_in[20];
  const float* Wte = (const float*)d_in[21]; const float* bte = (const float*)d_in[22];
  const float* Wtg = (const float*)d_in[23]; const float* btg = (const float*)d_in[24];

  float* ret = (float*)d_out;                 // [2,512,128]
  float* tri = ret + (size_t)BB*NN*DD;        // [2,512,512,8]

  cudaFuncSetAttribute(k_main, cudaFuncAttributeMaxDynamicSharedMemorySize, SMEM_BYTES);

  k_pre0<<<1, 256>>>(graph, Wmg, bm1, bm2, bme, bmg, Wtg, bt1, bt2, bte, btg);
  k_pre1<<<BB*NN/8, 256>>>(node, hidden, Wm1, Wm2, Wo1, Wt1, Wt2, bo1, bo2);
  k_init_msgs<<<(BB*NN*DD)/256, 256>>>();
  k_main<<<dim3(NN/RB, NN/SC, BB), NTHR, SMEM_BYTES>>>(edge, adjm, Wme, Wte, tri);
  k_out<<<BB*NN/16, 256>>>(Wo2, ret);
}